// round 15
// baseline (speedup 1.0000x reference)
#include <cuda_runtime.h>
#include <cuda_fp16.h>
#include <cstdint>

namespace {

constexpr int THREADS = 128;             // 4 warps/CTA, 6 CTAs/SM -> 24 warps
constexpr int MT      = 2;               // 16-row m-tiles per warp
constexpr int WARP_M  = 16 * MT;         // 32 rows / warp
constexpr int NWARP   = 4;
constexpr int CTA_M   = NWARP * WARP_M;  // 128 rows / CTA

// One flat per-lane permuted weight table; sections at compile-time offsets.
constexpr int OFF_D0 = 0;            // 8*1*32 = 256
constexpr int OFF_C0 = 256;          // 256
constexpr int OFF_D1 = 512;          // 128
constexpr int OFF_C1 = 640;          // 512
constexpr int OFF_C2 = 1152;         // 512
constexpr int OFF_C3 = 1664;         // 64
constexpr int TAB_SZ = 1728;         // 27648 B -> 6 CTAs = 166 KB

__device__ __forceinline__ uint32_t h2u(float x, float y) {
    __half2 h = __floats2half2_rn(x, y);
    return *reinterpret_cast<uint32_t*>(&h);
}
// Fused relu + pack: lo = relu(rn(x)), hi = relu(rn(y)). One SASS op.
__device__ __forceinline__ uint32_t cvt_relu2(float x, float y) {
    uint32_t r;
    asm("cvt.rn.relu.f16x2.f32 %0, %1, %2;\n" : "=r"(r) : "f"(y), "f"(x));
    return r;
}
// Packed-half relu.
__device__ __forceinline__ uint32_t hmax0_2(uint32_t p) {
    __half2 h = *reinterpret_cast<__half2*>(&p);
    __half2 r = __hmax2(h, __half2(__ushort_as_half(0), __ushort_as_half(0)));
    return *reinterpret_cast<uint32_t*>(&r);
}

__device__ __forceinline__ void mma16816(float c[4], const uint32_t a[4],
                                         uint32_t b0, uint32_t b1) {
    asm volatile(
        "mma.sync.aligned.m16n8k16.row.col.f32.f16.f16.f32 "
        "{%0,%1,%2,%3},{%4,%5,%6,%7},{%8,%9},{%0,%1,%2,%3};\n"
        : "+f"(c[0]), "+f"(c[1]), "+f"(c[2]), "+f"(c[3])
        : "r"(a[0]), "r"(a[1]), "r"(a[2]), "r"(a[3]), "r"(b0), "r"(b1));
}
// f16-accumulator variant: D/C are 2 packed f16x2 regs; D reg layout equals
// the next layer's A-fragment register layout (row g pair, row g+8 pair).
__device__ __forceinline__ void mma16816h(uint32_t c[2], const uint32_t a[4],
                                          uint32_t b0, uint32_t b1) {
    asm volatile(
        "mma.sync.aligned.m16n8k16.row.col.f16.f16.f16.f16 "
        "{%0,%1},{%2,%3,%4,%5},{%6,%7},{%0,%1};\n"
        : "+r"(c[0]), "+r"(c[1])
        : "r"(a[0]), "r"(a[1]), "r"(a[2]), "r"(a[3]), "r"(b0), "r"(b1));
}

// Stage a [Nout x Kin] f32 row-major weight matrix into the permuted table.
// Per-k-tile mode (2 bits each in `modes`):
//   0 = identity, 1 = gmem K-perm, 2 = density shift (c0 k-tile 1)
__device__ void stage_perm(uint4* dst, const float* __restrict__ W, int Nout,
                           int Kin, int NPH, int CH, int modes, int tid) {
    const int total = NPH * CH * 32;
    for (int e = tid; e < total; e += THREADS) {
        int lane = e & 31;
        int c    = (e >> 5) % CH;
        int nph  = e / (32 * CH);
        int row  = (nph >> 1) * 16 + (nph & 1) * 8 + (lane >> 2);
        int q    = lane & 3;
        auto rd = [&](int cc) -> float {
            return (cc >= 0 && row < Nout && cc < Kin) ? W[row * Kin + cc] : 0.0f;
        };
        auto pack = [&](int kt, int half) -> uint32_t {
            int mode = (modes >> (2 * kt)) & 3;
            int base = kt * 16;
            int t    = 2 * q + (half ? 8 : 0);
            int ca, cb;
            if (mode == 1) {
                ca = base + 4 * q + (half ? 2 : 0);
                cb = ca + 1;
            } else if (mode == 2) {
                ca = (t == 0) ? -1 : 15 + t;
                cb = 15 + t + 1;
            } else {
                ca = base + t;
                cb = ca + 1;
            }
            return h2u(rd(ca), rd(cb));
        };
        uint4 v;
        v.x = pack(2 * c,     0);
        v.y = pack(2 * c,     1);
        v.z = pack(2 * c + 1, 0);
        v.w = pack(2 * c + 1, 1);
        dst[e] = v;
    }
}

// f32-accumulator chained relu layer (d0, c0).
template <int KT, int NP>
__device__ __forceinline__ void layer_chain(const uint32_t (&A)[MT][4][4],
                                            const uint4* __restrict__ pw,
                                            uint32_t (&O)[MT][4][4]) {
    constexpr int CH = KT / 2;
#pragma unroll
    for (int np = 0; np < NP; np++) {
        float acc[MT][2][4];
#pragma unroll
        for (int m = 0; m < MT; m++)
#pragma unroll
            for (int h = 0; h < 2; h++)
#pragma unroll
                for (int e = 0; e < 4; e++) acc[m][h][e] = 0.0f;
#pragma unroll
        for (int h = 0; h < 2; h++) {
#pragma unroll
            for (int c = 0; c < CH; c++) {
                uint4 v = pw[((np * 2 + h) * CH + c) * 32];
#pragma unroll
                for (int m = 0; m < MT; m++) {
                    mma16816(acc[m][h], A[m][2 * c],     v.x, v.y);
                    mma16816(acc[m][h], A[m][2 * c + 1], v.z, v.w);
                }
            }
        }
#pragma unroll
        for (int m = 0; m < MT; m++) {
            O[m][np][0] = cvt_relu2(acc[m][0][0], acc[m][0][1]);
            O[m][np][1] = cvt_relu2(acc[m][0][2], acc[m][0][3]);
            O[m][np][2] = cvt_relu2(acc[m][1][0], acc[m][1][1]);
            O[m][np][3] = cvt_relu2(acc[m][1][2], acc[m][1][3]);
        }
    }
}

// f16-accumulator chained relu layer (c1, c2): 1.5x tensor-pipe rate, and the
// D registers ARE the next A-fragment registers (relu via one HMNMX2 each).
template <int KT, int NP>
__device__ __forceinline__ void layer_chain_h(const uint32_t (&A)[MT][4][4],
                                              const uint4* __restrict__ pw,
                                              uint32_t (&O)[MT][4][4]) {
    constexpr int CH = KT / 2;
#pragma unroll
    for (int np = 0; np < NP; np++) {
        uint32_t acc[MT][2][2];
#pragma unroll
        for (int m = 0; m < MT; m++)
#pragma unroll
            for (int h = 0; h < 2; h++)
                acc[m][h][0] = acc[m][h][1] = 0u;
#pragma unroll
        for (int h = 0; h < 2; h++) {
#pragma unroll
            for (int c = 0; c < CH; c++) {
                uint4 v = pw[((np * 2 + h) * CH + c) * 32];
#pragma unroll
                for (int m = 0; m < MT; m++) {
                    mma16816h(acc[m][h], A[m][2 * c],     v.x, v.y);
                    mma16816h(acc[m][h], A[m][2 * c + 1], v.z, v.w);
                }
            }
        }
#pragma unroll
        for (int m = 0; m < MT; m++) {
            O[m][np][0] = hmax0_2(acc[m][0][0]);  // row g,   h=0 cols
            O[m][np][1] = hmax0_2(acc[m][0][1]);  // row g+8
            O[m][np][2] = hmax0_2(acc[m][1][0]);  // row g,   h=1 cols (+8)
            O[m][np][3] = hmax0_2(acc[m][1][1]);  // row g+8
        }
    }
}

}  // namespace

__global__ void __launch_bounds__(THREADS, 6)
nerf_fused_kernel(const float* __restrict__ hash, const float* __restrict__ sh,
                  const float* __restrict__ d0, const float* __restrict__ d1,
                  const float* __restrict__ c0, const float* __restrict__ c1,
                  const float* __restrict__ c2, const float* __restrict__ c3,
                  float* __restrict__ out, int n_tiles) {
    __shared__ uint4 tab[TAB_SZ];
    const int tid  = threadIdx.x;
    const int warp = tid >> 5;
    const int lane = tid & 31;
    const int g    = lane >> 2;   // row-in-tile-half
    const int q    = lane & 3;    // column group

    // ---- Stage permuted weights once per CTA ----
    stage_perm(tab + OFF_D0, d0, 64, 32, 8, 1, 0b0101, tid);
    stage_perm(tab + OFF_C0, c0, 64, 31, 8, 1, 0b1001, tid);
    stage_perm(tab + OFF_D1, d1, 16, 64, 2, 2, 0, tid);
    stage_perm(tab + OFF_C1, c1, 64, 64, 8, 2, 0, tid);
    stage_perm(tab + OFF_C2, c2, 64, 64, 8, 2, 0, tid);
    stage_perm(tab + OFF_C3, c3,  3, 64, 1, 2, 0, tid);
    __syncthreads();  // only block barrier

    const uint4* pwl = tab + lane;
    const float4* hash4 = reinterpret_cast<const float4*>(hash);  // row = 8 f4
    const float4* sh4   = reinterpret_cast<const float4*>(sh);    // row = 4 f4
    const unsigned FULL = 0xffffffffu;

    for (int tile = blockIdx.x; tile < n_tiles; tile += gridDim.x) {
        const int row0 = tile * CTA_M + warp * WARP_M;

        uint32_t Aa[MT][4][4];  // ping
        uint32_t Ab[MT][4][4];  // pong; Ab[m][0..1] doubles as 32-wide input

        // ---- hash A frags: one LDG.128 per row-half per k-tile (K-perm) ----
#pragma unroll
        for (int m = 0; m < MT; m++) {
#pragma unroll
            for (int kt = 0; kt < 2; kt++) {
                float4 v0 = __ldcs(hash4 + (row0 + m * 16 + g) * 8 + kt * 4 + q);
                float4 v1 = __ldcs(hash4 + (row0 + m * 16 + g + 8) * 8 + kt * 4 + q);
                Ab[m][kt][0] = h2u(v0.x, v0.y);
                Ab[m][kt][1] = h2u(v1.x, v1.y);
                Ab[m][kt][2] = h2u(v0.z, v0.w);
                Ab[m][kt][3] = h2u(v1.z, v1.w);
            }
        }

        // ---- d0: relu(hash @ d0^T), f32 acc ----
        layer_chain<2, 4>(Ab, pwl + OFF_D0, Aa);

        // ---- sh loads issued NOW (into dead Ab[m][0]); d1 hides the latency
#pragma unroll
        for (int m = 0; m < MT; m++) {
            float4 v0 = __ldcs(sh4 + (row0 + m * 16 + g) * 4 + q);
            float4 v1 = __ldcs(sh4 + (row0 + m * 16 + g + 8) * 4 + q);
            Ab[m][0][0] = h2u(v0.x, v0.y);
            Ab[m][0][1] = h2u(v1.x, v1.y);
            Ab[m][0][2] = h2u(v0.z, v0.w);
            Ab[m][0][3] = h2u(v1.z, v1.w);
        }

        // ---- d1: h @ d1^T (f32 acc) -> sigma to gmem; raw output = c0's
        //      k-tile-1 A (concat shift lives in w_c0) ----
#pragma unroll
        for (int m = 0; m < MT; m++) {
            float dacc[2][4];
#pragma unroll
            for (int h = 0; h < 2; h++)
#pragma unroll
                for (int e = 0; e < 4; e++) dacc[h][e] = 0.0f;
#pragma unroll
            for (int h = 0; h < 2; h++) {
#pragma unroll
                for (int c = 0; c < 2; c++) {
                    uint4 v = pwl[OFF_D1 + (h * 2 + c) * 32];
                    mma16816(dacc[h], Aa[m][2 * c],     v.x, v.y);
                    mma16816(dacc[h], Aa[m][2 * c + 1], v.z, v.w);
                }
            }
            if (q == 0) {  // sigma = D col 0 (f32, exact)
                out[(row0 + m * 16 + g) * 4 + 3]     = dacc[0][0];
                out[(row0 + m * 16 + g + 8) * 4 + 3] = dacc[0][2];
            }
            Ab[m][1][0] = h2u(dacc[0][0], dacc[0][1]);
            Ab[m][1][1] = h2u(dacc[0][2], dacc[0][3]);
            Ab[m][1][2] = h2u(dacc[1][0], dacc[1][1]);
            Ab[m][1][3] = h2u(dacc[1][2], dacc[1][3]);
        }

        // ---- c0 (f32 acc), c1/c2 (f16 acc, 1.5x rate) ----
        layer_chain<2, 4>(Ab, pwl + OFF_C0, Aa);
        layer_chain_h<4, 4>(Aa, pwl + OFF_C1, Ab);
        layer_chain_h<4, 4>(Ab, pwl + OFF_C2, Aa);

        // ---- c3: color, f32 acc (cols 0..2 of one 8-wide n-tile) ----
        {
            float cacc[MT][4];
#pragma unroll
            for (int m = 0; m < MT; m++)
#pragma unroll
                for (int e = 0; e < 4; e++) cacc[m][e] = 0.0f;
#pragma unroll
            for (int c = 0; c < 2; c++) {
                uint4 v = pwl[OFF_C3 + c * 32];
#pragma unroll
                for (int m = 0; m < MT; m++) {
                    mma16816(cacc[m], Aa[m][2 * c],     v.x, v.y);
                    mma16816(cacc[m], Aa[m][2 * c + 1], v.z, v.w);
                }
            }
#pragma unroll
            for (int m = 0; m < MT; m++) {
                float b0c = __shfl_down_sync(FULL, cacc[m][0], 1);
                float b1c = __shfl_down_sync(FULL, cacc[m][2], 1);
                if (q == 0) {  // color; sigma already written
                    int r0 = (row0 + m * 16 + g) * 4;
                    int r1 = (row0 + m * 16 + g + 8) * 4;
                    *reinterpret_cast<float2*>(out + r0) =
                        make_float2(cacc[m][0], cacc[m][1]);
                    out[r0 + 2] = b0c;
                    *reinterpret_cast<float2*>(out + r1) =
                        make_float2(cacc[m][2], cacc[m][3]);
                    out[r1 + 2] = b1c;
                }
            }
        }
    }
}

extern "C" void kernel_launch(void* const* d_in, const int* in_sizes, int n_in,
                              void* d_out, int out_size) {
    const float* hash = (const float*)d_in[0];  // [N, 32]
    const float* sh   = (const float*)d_in[1];  // [N, 16]
    const float* d0   = (const float*)d_in[2];  // [64, 32]
    const float* d1   = (const float*)d_in[3];  // [16, 64]
    const float* c0   = (const float*)d_in[4];  // [64, 31]
    const float* c1   = (const float*)d_in[5];  // [64, 64]
    const float* c2   = (const float*)d_in[6];  // [64, 64]
    const float* c3   = (const float*)d_in[7];  // [3, 64]
    float* out = (float*)d_out;                 // [N, 4]

    const int n       = in_sizes[0] / 32;
    const int n_tiles = n / CTA_M;  // 16384

    int grid = 148 * 6;  // persistent, 6 CTAs/SM, 24 warps/SM
    if (grid > n_tiles) grid = n_tiles;

    nerf_fused_kernel<<<grid, THREADS>>>(hash, sh, d0, d1, c0, c1, c2, c3, out,
                                         n_tiles);
}